// round 1
// baseline (speedup 1.0000x reference)
#include <cuda_runtime.h>

#define NSEQ   2048
#define DIM    1024
#define HEADS  16
#define DH     64
#define INNER  1024
#define KV2    2048

// ALPHA * DIM_HEAD^-0.5 = 0.45 * 0.125
#define C_RAW  0.05625f
#define C_H    0.55f

// ---------------- scratch (static device globals; no allocations) -------------
__device__ float g_xn[NSEQ * DIM];
__device__ float g_q [NSEQ * INNER];
__device__ float g_kv[NSEQ * KV2];
__device__ float g_o [NSEQ * INNER];
__device__ float g_attn[(size_t)HEADS * NSEQ * NSEQ];

// ---------------- layernorm ---------------------------------------------------
__global__ void __launch_bounds__(256) ln_kernel(
    const float* __restrict__ x, const float* __restrict__ g,
    const float* __restrict__ b, float* __restrict__ xn)
{
    __shared__ float r1[8], r2[8];
    int row = blockIdx.x;
    int tid = threadIdx.x;
    const float4 v  = ((const float4*)(x + (size_t)row * DIM))[tid];

    float s  = v.x + v.y + v.z + v.w;
    float ss = v.x * v.x + v.y * v.y + v.z * v.z + v.w * v.w;
    #pragma unroll
    for (int o = 16; o; o >>= 1) {
        s  += __shfl_xor_sync(0xffffffffu, s,  o);
        ss += __shfl_xor_sync(0xffffffffu, ss, o);
    }
    int lane = tid & 31, wid = tid >> 5;
    if (lane == 0) { r1[wid] = s; r2[wid] = ss; }
    __syncthreads();
    float ts = 0.f, tss = 0.f;
    #pragma unroll
    for (int w = 0; w < 8; ++w) { ts += r1[w]; tss += r2[w]; }

    float mu  = ts * (1.0f / DIM);
    float var = tss * (1.0f / DIM) - mu * mu;
    float inv = rsqrtf(var + 1e-5f);

    float4 gg = ((const float4*)g)[tid];
    float4 bb = ((const float4*)b)[tid];
    float4 o;
    o.x = (v.x - mu) * inv * gg.x + bb.x;
    o.y = (v.y - mu) * inv * gg.y + bb.y;
    o.z = (v.z - mu) * inv * gg.z + bb.z;
    o.w = (v.w - mu) * inv * gg.w + bb.w;
    ((float4*)(xn + (size_t)row * DIM))[tid] = o;
}

// ---------------- generic batched SGEMM (C = A @ B [+bias]) -------------------
// Tiles: BM=128, BN=64, BK=16; 256 threads; 8x4 per thread.
// Requires: M % 128 == 0, N % 64 == 0, K % 16 == 0 (true for all call sites).
__global__ void __launch_bounds__(256) sgemm_nn(
    const float* __restrict__ A, const float* __restrict__ B, float* __restrict__ C,
    int M, int N, int K, int lda, int ldb, int ldc,
    long long sA, long long sB, long long sC,
    const float* __restrict__ bias)
{
    __shared__ float As[16][128];
    __shared__ float Bs[16][64];

    int z = blockIdx.z;
    A += (size_t)z * sA;  B += (size_t)z * sB;  C += (size_t)z * sC;

    int tm = blockIdx.y * 128;
    int tn = blockIdx.x * 64;
    int tid = threadIdx.x;
    int tx = tid & 15;     // N dir, 16 * 4 = 64
    int ty = tid >> 4;     // M dir, 16 * 8 = 128

    float acc[8][4];
    #pragma unroll
    for (int m = 0; m < 8; ++m)
        #pragma unroll
        for (int n = 0; n < 4; ++n) acc[m][n] = 0.f;

    for (int k0 = 0; k0 < K; k0 += 16) {
        #pragma unroll
        for (int l = 0; l < 2; ++l) {
            int lin = tid + l * 256;        // float4 index 0..511
            int r   = lin >> 2;             // row 0..127
            int kk  = (lin & 3) << 2;       // k: 0,4,8,12
            float4 av = *(const float4*)(A + (size_t)(tm + r) * lda + k0 + kk);
            As[kk + 0][r] = av.x; As[kk + 1][r] = av.y;
            As[kk + 2][r] = av.z; As[kk + 3][r] = av.w;
        }
        {
            int r  = tid >> 4;              // k row 0..15
            int nn = (tid & 15) << 2;       // n: 0..60
            float4 bv = *(const float4*)(B + (size_t)(k0 + r) * ldb + tn + nn);
            *(float4*)&Bs[r][nn] = bv;
        }
        __syncthreads();
        #pragma unroll
        for (int k = 0; k < 16; ++k) {
            float ra[8];
            #pragma unroll
            for (int m = 0; m < 8; ++m) ra[m] = As[k][ty * 8 + m];
            float4 bv = *(float4*)&Bs[k][tx * 4];
            float rb[4] = {bv.x, bv.y, bv.z, bv.w};
            #pragma unroll
            for (int m = 0; m < 8; ++m)
                #pragma unroll
                for (int n = 0; n < 4; ++n)
                    acc[m][n] += ra[m] * rb[n];
        }
        __syncthreads();
    }

    float bb0 = 0.f, bb1 = 0.f, bb2 = 0.f, bb3 = 0.f;
    if (bias) {
        bb0 = bias[tn + tx * 4 + 0];
        bb1 = bias[tn + tx * 4 + 1];
        bb2 = bias[tn + tx * 4 + 2];
        bb3 = bias[tn + tx * 4 + 3];
    }
    #pragma unroll
    for (int m = 0; m < 8; ++m) {
        float4 o;
        o.x = acc[m][0] + bb0;
        o.y = acc[m][1] + bb1;
        o.z = acc[m][2] + bb2;
        o.w = acc[m][3] + bb3;
        *(float4*)(C + (size_t)(tm + ty * 8 + m) * ldc + tn + tx * 4) = o;
    }
}

// ---------------- Q @ K^T with fused blend epilogue ---------------------------
// Per head z: raw = q_h (2048x64) @ k_h^T (64x2048)
// blended = C_RAW * raw + C_H * h_in   written straight into d_out blend region.
__global__ void __launch_bounds__(256) qk_blend(
    const float* __restrict__ Q, const float* __restrict__ Kk,
    const float* __restrict__ Hin, float* __restrict__ Cb)
{
    __shared__ float As[16][128];
    __shared__ float Bs[16][128];

    int h = blockIdx.z;
    const float* Aq = Q  + h * DH;                 // lda = INNER
    const float* Bk = Kk + h * DH;                 // ldb = KV2
    size_t hoff = (size_t)h * NSEQ * NSEQ;

    int ti = blockIdx.y * 128;
    int tj = blockIdx.x * 128;
    int tid = threadIdx.x;
    int tx = tid & 15;   // j dir, 16*8
    int ty = tid >> 4;   // i dir, 16*8

    float acc[8][8];
    #pragma unroll
    for (int m = 0; m < 8; ++m)
        #pragma unroll
        for (int n = 0; n < 8; ++n) acc[m][n] = 0.f;

    for (int k0 = 0; k0 < DH; k0 += 16) {
        #pragma unroll
        for (int l = 0; l < 2; ++l) {
            int lin = tid + l * 256;
            int r   = lin >> 2;
            int kk  = (lin & 3) << 2;
            float4 av = *(const float4*)(Aq + (size_t)(ti + r) * INNER + k0 + kk);
            As[kk + 0][r] = av.x; As[kk + 1][r] = av.y;
            As[kk + 2][r] = av.z; As[kk + 3][r] = av.w;
            float4 bv = *(const float4*)(Bk + (size_t)(tj + r) * KV2 + k0 + kk);
            Bs[kk + 0][r] = bv.x; Bs[kk + 1][r] = bv.y;
            Bs[kk + 2][r] = bv.z; Bs[kk + 3][r] = bv.w;
        }
        __syncthreads();
        #pragma unroll
        for (int k = 0; k < 16; ++k) {
            float ra[8], rb[8];
            #pragma unroll
            for (int m = 0; m < 8; ++m) ra[m] = As[k][ty * 8 + m];
            #pragma unroll
            for (int n = 0; n < 8; ++n) rb[n] = Bs[k][tx * 8 + n];
            #pragma unroll
            for (int m = 0; m < 8; ++m)
                #pragma unroll
                for (int n = 0; n < 8; ++n)
                    acc[m][n] += ra[m] * rb[n];
        }
        __syncthreads();
    }

    #pragma unroll
    for (int m = 0; m < 8; ++m) {
        size_t off = hoff + (size_t)(ti + ty * 8 + m) * NSEQ + tj + tx * 8;
        float4 h0 = *(const float4*)(Hin + off);
        float4 h1 = *(const float4*)(Hin + off + 4);
        float4 o0, o1;
        o0.x = C_RAW * acc[m][0] + C_H * h0.x;
        o0.y = C_RAW * acc[m][1] + C_H * h0.y;
        o0.z = C_RAW * acc[m][2] + C_H * h0.z;
        o0.w = C_RAW * acc[m][3] + C_H * h0.w;
        o1.x = C_RAW * acc[m][4] + C_H * h1.x;
        o1.y = C_RAW * acc[m][5] + C_H * h1.y;
        o1.z = C_RAW * acc[m][6] + C_H * h1.z;
        o1.w = C_RAW * acc[m][7] + C_H * h1.w;
        *(float4*)(Cb + off)     = o0;
        *(float4*)(Cb + off + 4) = o1;
    }
}

// ---------------- fused talking-heads: mix_pre -> softmax -> mix_post ---------
// One CTA per query row i. All 16 heads' 2048-wide rows live in 128 KB smem.
// All column-wise transforms are thread-exclusive per column (no races).
__global__ void __launch_bounds__(256) mix_softmax(
    const float* __restrict__ blended, const float* __restrict__ mixpre,
    const float* __restrict__ mixpost, float* __restrict__ attn)
{
    extern __shared__ float tile[];          // HEADS * NSEQ floats
    __shared__ float mp[256], mq[256], red[8];

    int i   = blockIdx.x;
    int tid = threadIdx.x;
    int lane = tid & 31, wid = tid >> 5;

    mp[tid] = mixpre[tid];
    mq[tid] = mixpost[tid];

    // load 16 head-rows for this query
    for (int h = 0; h < HEADS; ++h) {
        const float* src = blended + (size_t)h * NSEQ * NSEQ + (size_t)i * NSEQ;
        for (int j = tid; j < NSEQ; j += 256) tile[h * NSEQ + j] = src[j];
    }
    __syncthreads();

    // talking-heads pre: dots[g] = sum_h blended[h] * mp[h][g]   (in place, per column)
    for (int j = tid; j < NSEQ; j += 256) {
        float v[HEADS], d[HEADS];
        #pragma unroll
        for (int h = 0; h < HEADS; ++h) v[h] = tile[h * NSEQ + j];
        #pragma unroll
        for (int g = 0; g < HEADS; ++g) {
            float s = 0.f;
            #pragma unroll
            for (int h = 0; h < HEADS; ++h) s += v[h] * mp[h * HEADS + g];
            d[g] = s;
        }
        #pragma unroll
        for (int g = 0; g < HEADS; ++g) tile[g * NSEQ + j] = d[g];
    }
    __syncthreads();

    // softmax over j for each g
    for (int g = 0; g < HEADS; ++g) {
        float* row = tile + g * NSEQ;
        float m = -1e30f;
        for (int j = tid; j < NSEQ; j += 256) m = fmaxf(m, row[j]);
        #pragma unroll
        for (int o = 16; o; o >>= 1) m = fmaxf(m, __shfl_xor_sync(0xffffffffu, m, o));
        if (lane == 0) red[wid] = m;
        __syncthreads();
        float gm = red[0];
        #pragma unroll
        for (int w = 1; w < 8; ++w) gm = fmaxf(gm, red[w]);
        __syncthreads();

        float s = 0.f;
        for (int j = tid; j < NSEQ; j += 256) {
            float e = __expf(row[j] - gm);
            row[j] = e;
            s += e;
        }
        #pragma unroll
        for (int o = 16; o; o >>= 1) s += __shfl_xor_sync(0xffffffffu, s, o);
        if (lane == 0) red[wid] = s;
        __syncthreads();
        float gs = 0.f;
        #pragma unroll
        for (int w = 0; w < 8; ++w) gs += red[w];
        __syncthreads();

        float inv = 1.0f / gs;
        for (int j = tid; j < NSEQ; j += 256) row[j] *= inv;
    }
    __syncthreads();

    // talking-heads post + write to scratch
    for (int j = tid; j < NSEQ; j += 256) {
        float v[HEADS];
        #pragma unroll
        for (int h = 0; h < HEADS; ++h) v[h] = tile[h * NSEQ + j];
        #pragma unroll
        for (int g = 0; g < HEADS; ++g) {
            float s = 0.f;
            #pragma unroll
            for (int h = 0; h < HEADS; ++h) s += v[h] * mq[h * HEADS + g];
            attn[(size_t)g * NSEQ * NSEQ + (size_t)i * NSEQ + j] = s;
        }
    }
}

// ---------------- launch -------------------------------------------------------
extern "C" void kernel_launch(void* const* d_in, const int* in_sizes, int n_in,
                              void* d_out, int out_size)
{
    (void)in_sizes; (void)n_in; (void)out_size;
    const float* x     = (const float*)d_in[0];
    const float* h     = (const float*)d_in[1];
    const float* ln_g  = (const float*)d_in[2];
    const float* ln_b  = (const float*)d_in[3];
    const float* Wq    = (const float*)d_in[4];
    const float* Wkv   = (const float*)d_in[5];
    const float* mpre  = (const float*)d_in[6];
    const float* mpost = (const float*)d_in[7];
    const float* Wout  = (const float*)d_in[8];
    const float* bout  = (const float*)d_in[9];

    float* out     = (float*)d_out;
    float* blended = out + (size_t)NSEQ * DIM;

    float *xn, *q, *kv, *o, *attn;
    cudaGetSymbolAddress((void**)&xn,   g_xn);
    cudaGetSymbolAddress((void**)&q,    g_q);
    cudaGetSymbolAddress((void**)&kv,   g_kv);
    cudaGetSymbolAddress((void**)&o,    g_o);
    cudaGetSymbolAddress((void**)&attn, g_attn);

    // 1. layernorm
    ln_kernel<<<NSEQ, 256>>>(x, ln_g, ln_b, xn);

    // 2. q = xn @ Wq   (2048x1024 @ 1024x1024)
    sgemm_nn<<<dim3(INNER / 64, NSEQ / 128, 1), 256>>>(
        xn, Wq, q, NSEQ, INNER, DIM, DIM, INNER, INNER, 0, 0, 0, nullptr);

    // 3. kv = xn @ Wkv (2048x1024 @ 1024x2048)
    sgemm_nn<<<dim3(KV2 / 64, NSEQ / 128, 1), 256>>>(
        xn, Wkv, kv, NSEQ, KV2, DIM, DIM, KV2, KV2, 0, 0, 0, nullptr);

    // 4. blended = 0.05625 * (q @ k^T) + 0.55 * h   -> directly into d_out
    qk_blend<<<dim3(NSEQ / 128, NSEQ / 128, HEADS), 256>>>(q, kv, h, blended);

    // 5. fused mix_pre -> softmax -> mix_post
    cudaFuncSetAttribute(mix_softmax, cudaFuncAttributeMaxDynamicSharedMemorySize,
                         HEADS * NSEQ * (int)sizeof(float));
    mix_softmax<<<NSEQ, 256, HEADS * NSEQ * sizeof(float)>>>(blended, mpre, mpost, attn);

    // 6. per-head out: o[:, g*64:(g+1)*64] = attn[g] @ v_g
    sgemm_nn<<<dim3(1, NSEQ / 128, HEADS), 256>>>(
        attn, kv + INNER, o, NSEQ, DH, NSEQ, NSEQ, KV2, INNER,
        (long long)NSEQ * NSEQ, (long long)DH, (long long)DH, nullptr);

    // 7. out = o @ Wout + bout
    sgemm_nn<<<dim3(DIM / 64, NSEQ / 128, 1), 256>>>(
        o, Wout, out, NSEQ, DIM, INNER, INNER, DIM, DIM, 0, 0, 0, bout);
}

// round 3
// speedup vs baseline: 1.6036x; 1.6036x over previous
#include <cuda_runtime.h>
#include <cuda_bf16.h>
#include <cstdint>
#include <cstring>

#define NSEQ   2048
#define DIM    1024
#define HEADS  16
#define DH     64
#define INNER  1024
#define KV2    2048

#define C_RAW  0.05625f
#define C_H    0.55f

typedef __nv_bfloat16 bf16;

// ---------------- scratch (static device globals; no allocations) -------------
__device__ __align__(256) bf16 g_xn_hi[NSEQ * DIM],   g_xn_lo[NSEQ * DIM];
__device__ __align__(256) bf16 g_wqt_hi[INNER * DIM], g_wqt_lo[INNER * DIM];
__device__ __align__(256) bf16 g_wkvt_hi[KV2 * DIM],  g_wkvt_lo[KV2 * DIM];
__device__ __align__(256) bf16 g_wot_hi[DIM * INNER], g_wot_lo[DIM * INNER];
__device__ __align__(256) bf16 g_q_hi[NSEQ * INNER],  g_q_lo[NSEQ * INNER];
__device__ __align__(256) bf16 g_kv_hi[NSEQ * KV2],   g_kv_lo[NSEQ * KV2];
__device__ __align__(256) bf16 g_vt_hi[INNER * NSEQ], g_vt_lo[INNER * NSEQ];
__device__ __align__(256) bf16 g_at_hi[(size_t)HEADS * NSEQ * NSEQ];
__device__ __align__(256) bf16 g_at_lo[(size_t)HEADS * NSEQ * NSEQ];
__device__ __align__(256) bf16 g_o_hi[NSEQ * INNER],  g_o_lo[NSEQ * INNER];

// ---------------- helpers ------------------------------------------------------
__device__ __forceinline__ uint32_t smem_to_u32(const void* p) {
    uint32_t a;
    asm("{ .reg .u64 t; cvta.to.shared.u64 t, %1; cvt.u32.u64 %0, t; }"
        : "=r"(a) : "l"(p));
    return a;
}

__device__ __forceinline__ void ldmx4(uint32_t* r, uint32_t addr) {
    asm volatile("ldmatrix.sync.aligned.m8n8.x4.shared.b16 {%0,%1,%2,%3}, [%4];"
        : "=r"(r[0]), "=r"(r[1]), "=r"(r[2]), "=r"(r[3]) : "r"(addr));
}

__device__ __forceinline__ void mma_bf16(float* d, const uint32_t* a, const uint32_t* b) {
    asm volatile(
        "mma.sync.aligned.m16n8k16.row.col.f32.bf16.bf16.f32 "
        "{%0,%1,%2,%3}, {%4,%5,%6,%7}, {%8,%9}, {%0,%1,%2,%3};"
        : "+f"(d[0]), "+f"(d[1]), "+f"(d[2]), "+f"(d[3])
        : "r"(a[0]), "r"(a[1]), "r"(a[2]), "r"(a[3]), "r"(b[0]), "r"(b[1]));
}

__device__ __forceinline__ void cp16(uint32_t sdst, const void* gsrc) {
    asm volatile("cp.async.cg.shared.global [%0], [%1], 16;"
                 :: "r"(sdst), "l"(__cvta_generic_to_global(gsrc)));
}
#define CP_COMMIT() asm volatile("cp.async.commit_group;" ::: "memory")
#define CP_WAIT(n)  asm volatile("cp.async.wait_group %0;" :: "n"(n) : "memory")

__device__ __forceinline__ uint32_t pack2(bf16 a, bf16 b) {
    __nv_bfloat162 t; t.x = a; t.y = b;
    uint32_t r; memcpy(&r, &t, 4); return r;
}

__device__ __forceinline__ void split1(float v, bf16& h, bf16& l) {
    h = __float2bfloat16(v);
    l = __float2bfloat16(v - __bfloat162float(h));
}

// ---------------- layernorm + split --------------------------------------------
__global__ void __launch_bounds__(256) ln_split(
    const float* __restrict__ x, const float* __restrict__ g,
    const float* __restrict__ b, bf16* __restrict__ xh, bf16* __restrict__ xl)
{
    __shared__ float r1[8], r2[8];
    int row = blockIdx.x;
    int tid = threadIdx.x;
    const float4 v = ((const float4*)(x + (size_t)row * DIM))[tid];

    float s  = v.x + v.y + v.z + v.w;
    float ss = v.x * v.x + v.y * v.y + v.z * v.z + v.w * v.w;
    #pragma unroll
    for (int o = 16; o; o >>= 1) {
        s  += __shfl_xor_sync(0xffffffffu, s,  o);
        ss += __shfl_xor_sync(0xffffffffu, ss, o);
    }
    int lane = tid & 31, wid = tid >> 5;
    if (lane == 0) { r1[wid] = s; r2[wid] = ss; }
    __syncthreads();
    float ts = 0.f, tss = 0.f;
    #pragma unroll
    for (int w = 0; w < 8; ++w) { ts += r1[w]; tss += r2[w]; }

    float mu  = ts * (1.0f / DIM);
    float var = tss * (1.0f / DIM) - mu * mu;
    float inv = rsqrtf(var + 1e-5f);

    float4 gg = ((const float4*)g)[tid];
    float4 bb = ((const float4*)b)[tid];
    float o0 = (v.x - mu) * inv * gg.x + bb.x;
    float o1 = (v.y - mu) * inv * gg.y + bb.y;
    float o2 = (v.z - mu) * inv * gg.z + bb.z;
    float o3 = (v.w - mu) * inv * gg.w + bb.w;

    bf16 h0,l0,h1,l1,h2,l2,h3,l3;
    split1(o0,h0,l0); split1(o1,h1,l1); split1(o2,h2,l2); split1(o3,h3,l3);
    uint2 hw = make_uint2(pack2(h0,h1), pack2(h2,h3));
    uint2 lw = make_uint2(pack2(l0,l1), pack2(l2,l3));
    *(uint2*)(xh + (size_t)row * DIM + tid * 4) = hw;
    *(uint2*)(xl + (size_t)row * DIM + tid * 4) = lw;
}

// ---------------- transpose + split weights: W[K,N] fp32 -> Wt[N,K] hi/lo ------
__global__ void __launch_bounds__(256) tsplit(
    const float* __restrict__ src, bf16* __restrict__ dh, bf16* __restrict__ dl,
    int K, int N)
{
    __shared__ float t[32][33];
    int n0 = blockIdx.x * 32, k0 = blockIdx.y * 32;
    int x = threadIdx.x, y = threadIdx.y;
    #pragma unroll
    for (int i = y; i < 32; i += 8)
        t[i][x] = src[(size_t)(k0 + i) * N + n0 + x];
    __syncthreads();
    #pragma unroll
    for (int i = y; i < 32; i += 8) {
        float v = t[x][i];                 // = src[k0+x][n0+i]
        bf16 h, l; split1(v, h, l);
        dh[(size_t)(n0 + i) * K + k0 + x] = h;
        dl[(size_t)(n0 + i) * K + k0 + x] = l;
    }
}

// ---------------- transpose v part of kv (bf16) into vt [1024][2048] -----------
__global__ void __launch_bounds__(256) vtrans(
    const bf16* __restrict__ ih, const bf16* __restrict__ il,
    bf16* __restrict__ oh, bf16* __restrict__ ol)
{
    __shared__ bf16 th[32][33], tl[32][33];
    int c0 = blockIdx.x * 32, j0 = blockIdx.y * 32;
    int x = threadIdx.x, y = threadIdx.y;
    #pragma unroll
    for (int i = y; i < 32; i += 8) {
        th[i][x] = ih[(size_t)(j0 + i) * KV2 + INNER + c0 + x];
        tl[i][x] = il[(size_t)(j0 + i) * KV2 + INNER + c0 + x];
    }
    __syncthreads();
    #pragma unroll
    for (int i = y; i < 32; i += 8) {
        oh[(size_t)(c0 + i) * NSEQ + j0 + x] = th[x][i];
        ol[(size_t)(c0 + i) * NSEQ + j0 + x] = tl[x][i];
    }
}

// ---------------- async tile loader: ROWS x 64 bf16, rows padded to 144B -------
template<int ROWS>
__device__ __forceinline__ void ld_tile(uint32_t sdst, const bf16* src, int ld, int tid) {
    #pragma unroll
    for (int it = 0; it < ROWS * 8 / 256; ++it) {
        int lin = tid + it * 256;
        int r  = lin >> 3;
        int cB = (lin & 7) << 4;     // byte offset within 128B row payload
        cp16(sdst + r * 144 + cB, src + (size_t)r * ld + (cB >> 1));
    }
}

// ---------------- split-bf16 HMMA GEMM ------------------------------------------
// C[M=128 rows per CTA, N=BN] += (Ah+Al)[M,K] @ (Bh+Bl)[N,K]^T, fp32 accum.
// MODE 0: Cf = acc + bias   MODE 1: Chi/Clo = split(acc)   MODE 2: Cf = C_RAW*acc + C_H*Hin
template<int BN, int MODE>
__global__ void __launch_bounds__(256, 1) gemm_mma(
    const bf16* __restrict__ Ah, const bf16* __restrict__ Al,
    const bf16* __restrict__ Bh, const bf16* __restrict__ Bl,
    int K, int lda, int ldb,
    long long sA, long long sB, long long sC,
    float* __restrict__ Cf, bf16* __restrict__ Chi, bf16* __restrict__ Clo,
    int ldo, const float* __restrict__ bias, const float* __restrict__ Hin)
{
    constexpr int ROWB  = 144;            // 64 bf16 payload + 16B pad
    constexpr int ATB   = 128 * ROWB;
    constexpr int BTB   = BN * ROWB;
    constexpr int STAGE = 2 * ATB + 2 * BTB;
    constexpr int NW_M  = (BN == 128) ? 2 : 4;
    constexpr int NW_N  = 8 / NW_M;
    constexpr int WM    = 128 / NW_M;     // 64 or 32
    constexpr int WN    = BN / NW_N;      // 32
    constexpr int MF    = WM / 16;        // 4 or 2
    constexpr int NF    = WN / 8;         // 4

    extern __shared__ char smem[];
    uint32_t smb = smem_to_u32(smem);

    int tid = threadIdx.x, lane = tid & 31, wid = tid >> 5;
    int z = blockIdx.z;
    int tm = blockIdx.y * 128, tn = blockIdx.x * BN;
    int wm = wid / NW_N, wn = wid % NW_N;

    const bf16* pAh = Ah + (size_t)z * sA + (size_t)tm * lda;
    const bf16* pAl = Al + (size_t)z * sA + (size_t)tm * lda;
    const bf16* pBh = Bh + (size_t)z * sB + (size_t)tn * ldb;
    const bf16* pBl = Bl + (size_t)z * sB + (size_t)tn * ldb;

    float acc[MF][NF][4];
    #pragma unroll
    for (int i = 0; i < MF; ++i)
        #pragma unroll
        for (int j = 0; j < NF; ++j)
            #pragma unroll
            for (int q = 0; q < 4; ++q) acc[i][j][q] = 0.f;

    // per-lane ldmatrix address components (byte offsets inside tiles)
    const uint32_t aRow = (uint32_t)(wm * WM + (lane & 15)) * ROWB + ((lane >> 4) << 4);
    const uint32_t bRow = (uint32_t)(wn * WN + (lane & 7) + ((lane >> 4) << 3)) * ROWB
                        + (((lane >> 3) & 1) << 4);

    const int nc = K >> 6;

    // prologue: chunk 0 into buffer 0
    ld_tile<128>(smb,                 pAh, lda, tid);
    ld_tile<128>(smb + ATB,           pAl, lda, tid);
    ld_tile<BN >(smb + 2*ATB,         pBh, ldb, tid);
    ld_tile<BN >(smb + 2*ATB + BTB,   pBl, ldb, tid);
    CP_COMMIT();

    for (int c = 0; c < nc; ++c) {
        int buf = c & 1;
        if (c + 1 < nc) {
            uint32_t nb = smb + ((c + 1) & 1) * STAGE;
            int koff = (c + 1) << 6;
            ld_tile<128>(nb,               pAh + koff, lda, tid);
            ld_tile<128>(nb + ATB,         pAl + koff, lda, tid);
            ld_tile<BN >(nb + 2*ATB,       pBh + koff, ldb, tid);
            ld_tile<BN >(nb + 2*ATB + BTB, pBl + koff, ldb, tid);
            CP_COMMIT();
            CP_WAIT(1);
        } else {
            CP_WAIT(0);
        }
        __syncthreads();

        uint32_t base = smb + buf * STAGE;
        #pragma unroll
        for (int ks = 0; ks < 4; ++ks) {
            uint32_t ah[MF][4], al[MF][4], bh[NF][2], bl[NF][2];
            #pragma unroll
            for (int fm = 0; fm < MF; ++fm) {
                uint32_t ra = base + aRow + fm * 16 * ROWB + ks * 32;
                ldmx4(ah[fm], ra);
                ldmx4(al[fm], ra + ATB);
            }
            #pragma unroll
            for (int f2 = 0; f2 < NF / 2; ++f2) {
                uint32_t rb = base + 2*ATB + bRow + f2 * 16 * ROWB + ks * 32;
                uint32_t r4[4];
                ldmx4(r4, rb);
                bh[2*f2][0] = r4[0]; bh[2*f2][1] = r4[1];
                bh[2*f2+1][0] = r4[2]; bh[2*f2+1][1] = r4[3];
                ldmx4(r4, rb + BTB);
                bl[2*f2][0] = r4[0]; bl[2*f2][1] = r4[1];
                bl[2*f2+1][0] = r4[2]; bl[2*f2+1][1] = r4[3];
            }
            #pragma unroll
            for (int fm = 0; fm < MF; ++fm)
                #pragma unroll
                for (int fn = 0; fn < NF; ++fn) {
                    mma_bf16(acc[fm][fn], ah[fm], bh[fn]);
                    mma_bf16(acc[fm][fn], ah[fm], bl[fn]);
                    mma_bf16(acc[fm][fn], al[fm], bh[fn]);
                }
        }
        __syncthreads();
    }

    // -------- epilogue --------
    #pragma unroll
    for (int fm = 0; fm < MF; ++fm) {
        int row0 = tm + wm * WM + fm * 16 + (lane >> 2);
        #pragma unroll
        for (int fn = 0; fn < NF; ++fn) {
            int col = tn + wn * WN + fn * 8 + ((lane & 3) << 1);
            const float* a4 = acc[fm][fn];
            if (MODE == 0) {
                float b0 = bias[col], b1 = bias[col + 1];
                float* p0 = Cf + (size_t)z * sC + (size_t)row0 * ldo + col;
                float* p1 = Cf + (size_t)z * sC + (size_t)(row0 + 8) * ldo + col;
                float2 o0 = make_float2(a4[0] + b0, a4[1] + b1);
                float2 o1 = make_float2(a4[2] + b0, a4[3] + b1);
                *(float2*)p0 = o0;
                *(float2*)p1 = o1;
            } else if (MODE == 1) {
                bf16 h0,l0,h1,l1;
                split1(a4[0], h0, l0); split1(a4[1], h1, l1);
                size_t off0 = (size_t)z * sC + (size_t)row0 * ldo + col;
                *(uint32_t*)(Chi + off0) = pack2(h0, h1);
                *(uint32_t*)(Clo + off0) = pack2(l0, l1);
                split1(a4[2], h0, l0); split1(a4[3], h1, l1);
                size_t off1 = (size_t)z * sC + (size_t)(row0 + 8) * ldo + col;
                *(uint32_t*)(Chi + off1) = pack2(h0, h1);
                *(uint32_t*)(Clo + off1) = pack2(l0, l1);
            } else {
                size_t off0 = (size_t)z * sC + (size_t)row0 * ldo + col;
                size_t off1 = (size_t)z * sC + (size_t)(row0 + 8) * ldo + col;
                float2 hv0 = *(const float2*)(Hin + off0);
                float2 hv1 = *(const float2*)(Hin + off1);
                float2 o0 = make_float2(C_RAW * a4[0] + C_H * hv0.x,
                                        C_RAW * a4[1] + C_H * hv0.y);
                float2 o1 = make_float2(C_RAW * a4[2] + C_H * hv1.x,
                                        C_RAW * a4[3] + C_H * hv1.y);
                *(float2*)(Cf + off0) = o0;
                *(float2*)(Cf + off1) = o1;
            }
        }
    }
}

// ---------------- fused talking-heads: mix_pre -> softmax -> mix_post ---------
__global__ void __launch_bounds__(256) mix_softmax(
    const float* __restrict__ blended, const float* __restrict__ mixpre,
    const float* __restrict__ mixpost, bf16* __restrict__ ah, bf16* __restrict__ al)
{
    extern __shared__ float tile[];          // HEADS * NSEQ floats
    __shared__ float mp[256], mq[256], red[8];

    int i   = blockIdx.x;
    int tid = threadIdx.x;
    int lane = tid & 31, wid = tid >> 5;

    mp[tid] = mixpre[tid];
    mq[tid] = mixpost[tid];

    for (int h = 0; h < HEADS; ++h) {
        const float* src = blended + (size_t)h * NSEQ * NSEQ + (size_t)i * NSEQ;
        for (int j = tid; j < NSEQ; j += 256) tile[h * NSEQ + j] = src[j];
    }
    __syncthreads();

    for (int j = tid; j < NSEQ; j += 256) {
        float v[HEADS], d[HEADS];
        #pragma unroll
        for (int h = 0; h < HEADS; ++h) v[h] = tile[h * NSEQ + j];
        #pragma unroll
        for (int g = 0; g < HEADS; ++g) {
            float s = 0.f;
            #pragma unroll
            for (int h = 0; h < HEADS; ++h) s += v[h] * mp[h * HEADS + g];
            d[g] = s;
        }
        #pragma unroll
        for (int g = 0; g < HEADS; ++g) tile[g * NSEQ + j] = d[g];
    }
    __syncthreads();

    for (int g = 0; g < HEADS; ++g) {
        float* row = tile + g * NSEQ;
        float m = -1e30f;
        for (int j = tid; j < NSEQ; j += 256) m = fmaxf(m, row[j]);
        #pragma unroll
        for (int o = 16; o; o >>= 1) m = fmaxf(m, __shfl_xor_sync(0xffffffffu, m, o));
        if (lane == 0) red[wid] = m;
        __syncthreads();
        float gm = red[0];
        #pragma unroll
        for (int w = 1; w < 8; ++w) gm = fmaxf(gm, red[w]);
        __syncthreads();

        float s = 0.f;
        for (int j = tid; j < NSEQ; j += 256) {
            float e = __expf(row[j] - gm);
            row[j] = e;
            s += e;
        }
        #pragma unroll
        for (int o = 16; o; o >>= 1) s += __shfl_xor_sync(0xffffffffu, s, o);
        if (lane == 0) red[wid] = s;
        __syncthreads();
        float gs = 0.f;
        #pragma unroll
        for (int w = 0; w < 8; ++w) gs += red[w];
        __syncthreads();

        float inv = 1.0f / gs;
        for (int j = tid; j < NSEQ; j += 256) row[j] *= inv;
    }
    __syncthreads();

    for (int j = tid; j < NSEQ; j += 256) {
        float v[HEADS];
        #pragma unroll
        for (int h = 0; h < HEADS; ++h) v[h] = tile[h * NSEQ + j];
        #pragma unroll
        for (int g = 0; g < HEADS; ++g) {
            float s = 0.f;
            #pragma unroll
            for (int h = 0; h < HEADS; ++h) s += v[h] * mq[h * HEADS + g];
            size_t idx = (size_t)g * NSEQ * NSEQ + (size_t)i * NSEQ + j;
            bf16 hh, ll; split1(s, hh, ll);
            ah[idx] = hh; al[idx] = ll;
        }
    }
}

// ---------------- launch -------------------------------------------------------
extern "C" void kernel_launch(void* const* d_in, const int* in_sizes, int n_in,
                              void* d_out, int out_size)
{
    (void)in_sizes; (void)n_in; (void)out_size;
    const float* x     = (const float*)d_in[0];
    const float* h     = (const float*)d_in[1];
    const float* ln_g  = (const float*)d_in[2];
    const float* ln_b  = (const float*)d_in[3];
    const float* Wq    = (const float*)d_in[4];
    const float* Wkv   = (const float*)d_in[5];
    const float* mpre  = (const float*)d_in[6];
    const float* mpost = (const float*)d_in[7];
    const float* Wout  = (const float*)d_in[8];
    const float* bout  = (const float*)d_in[9];

    float* out     = (float*)d_out;
    float* blended = out + (size_t)NSEQ * DIM;

    bf16 *xnh,*xnl,*wqh,*wql,*wkh,*wkl,*woh,*wol,*qh,*ql,*kvh,*kvl,*vth,*vtl,*ath,*atl,*oh,*ol;
    cudaGetSymbolAddress((void**)&xnh, g_xn_hi);  cudaGetSymbolAddress((void**)&xnl, g_xn_lo);
    cudaGetSymbolAddress((void**)&wqh, g_wqt_hi); cudaGetSymbolAddress((void**)&wql, g_wqt_lo);
    cudaGetSymbolAddress((void**)&wkh, g_wkvt_hi);cudaGetSymbolAddress((void**)&wkl, g_wkvt_lo);
    cudaGetSymbolAddress((void**)&woh, g_wot_hi); cudaGetSymbolAddress((void**)&wol, g_wot_lo);
    cudaGetSymbolAddress((void**)&qh,  g_q_hi);   cudaGetSymbolAddress((void**)&ql,  g_q_lo);
    cudaGetSymbolAddress((void**)&kvh, g_kv_hi);  cudaGetSymbolAddress((void**)&kvl, g_kv_lo);
    cudaGetSymbolAddress((void**)&vth, g_vt_hi);  cudaGetSymbolAddress((void**)&vtl, g_vt_lo);
    cudaGetSymbolAddress((void**)&ath, g_at_hi);  cudaGetSymbolAddress((void**)&atl, g_at_lo);
    cudaGetSymbolAddress((void**)&oh,  g_o_hi);   cudaGetSymbolAddress((void**)&ol,  g_o_lo);

    // dynamic smem sizes: 2 stages * (A hi/lo 128 rows + B hi/lo BN rows) * 144B
    const int SM128 = 2 * (2 * 128 * 144 + 2 * 128 * 144);  // 147456
    const int SM64  = 2 * (2 * 128 * 144 + 2 *  64 * 144);  // 110592
    cudaFuncSetAttribute(gemm_mma<128,0>, cudaFuncAttributeMaxDynamicSharedMemorySize, SM128);
    cudaFuncSetAttribute(gemm_mma<128,1>, cudaFuncAttributeMaxDynamicSharedMemorySize, SM128);
    cudaFuncSetAttribute(gemm_mma<128,2>, cudaFuncAttributeMaxDynamicSharedMemorySize, SM128);
    cudaFuncSetAttribute(gemm_mma<64,1>,  cudaFuncAttributeMaxDynamicSharedMemorySize, SM64);
    cudaFuncSetAttribute(mix_softmax, cudaFuncAttributeMaxDynamicSharedMemorySize,
                         HEADS * NSEQ * (int)sizeof(float));

    // 1. layernorm + split
    ln_split<<<NSEQ, 256>>>(x, ln_g, ln_b, xnh, xnl);

    // 2. weight transpose+split
    tsplit<<<dim3(INNER/32, DIM/32), dim3(32,8)>>>(Wq,  wqh, wql, DIM, INNER);
    tsplit<<<dim3(KV2/32,   DIM/32), dim3(32,8)>>>(Wkv, wkh, wkl, DIM, KV2);
    tsplit<<<dim3(DIM/32, INNER/32), dim3(32,8)>>>(Wout,woh, wol, INNER, DIM);

    // 3. q = xn @ Wq  -> q hi/lo
    gemm_mma<128,1><<<dim3(INNER/128, NSEQ/128, 1), 256, SM128>>>(
        xnh, xnl, wqh, wql, DIM, DIM, DIM, 0, 0, 0,
        nullptr, qh, ql, INNER, nullptr, nullptr);

    // 4. kv = xn @ Wkv -> kv hi/lo
    gemm_mma<128,1><<<dim3(KV2/128, NSEQ/128, 1), 256, SM128>>>(
        xnh, xnl, wkh, wkl, DIM, DIM, DIM, 0, 0, 0,
        nullptr, kvh, kvl, KV2, nullptr, nullptr);

    // 5. transpose v -> vt [1024][2048]
    vtrans<<<dim3(INNER/32, NSEQ/32), dim3(32,8)>>>(kvh, kvl, vth, vtl);

    // 6. blended = C_RAW * (q @ k^T) + C_H * h  -> d_out
    gemm_mma<128,2><<<dim3(NSEQ/128, NSEQ/128, HEADS), 256, SM128>>>(
        qh, ql, kvh, kvl, DH, INNER, KV2, DH, DH, (long long)NSEQ*NSEQ,
        blended, nullptr, nullptr, NSEQ, nullptr, h);

    // 7. mix_pre -> softmax -> mix_post -> attn hi/lo
    mix_softmax<<<NSEQ, 256, HEADS * NSEQ * sizeof(float)>>>(blended, mpre, mpost, ath, atl);

    // 8. o[:, g*64:] = attn[g] @ v_g   (per-head, BN=64)
    gemm_mma<64,1><<<dim3(1, NSEQ/128, HEADS), 256, SM64>>>(
        ath, atl, vth, vtl, NSEQ, NSEQ, NSEQ,
        (long long)NSEQ*NSEQ, (long long)DH*NSEQ, (long long)DH,
        nullptr, oh, ol, INNER, nullptr, nullptr);

    // 9. out = o @ Wout + bout
    gemm_mma<128,0><<<dim3(DIM/128, NSEQ/128, 1), 256, SM128>>>(
        oh, ol, woh, wol, INNER, INNER, INNER, 0, 0, 0,
        out, nullptr, nullptr, DIM, bout, nullptr);
}

// round 4
// speedup vs baseline: 1.7250x; 1.0757x over previous
#include <cuda_runtime.h>
#include <cuda_bf16.h>
#include <cstdint>
#include <cstring>

#define NSEQ   2048
#define DIM    1024
#define HEADS  16
#define DH     64
#define INNER  1024
#define KV2    2048
#define QKV3   3072

#define C_RAW  0.05625f
#define C_H    0.55f

#define PITCH  2056   // floats per head-row in mix smem; 2056 % 32 == 8 -> bank = 8h+j

typedef __nv_bfloat16 bf16;

// ---------------- scratch (static device globals; no allocations) -------------
__device__ __align__(256) bf16 g_xn_hi[NSEQ * DIM],   g_xn_lo[NSEQ * DIM];
__device__ __align__(256) bf16 g_w1t_hi[QKV3 * DIM],  g_w1t_lo[QKV3 * DIM];  // [Wq^T; Wkv^T]
__device__ __align__(256) bf16 g_wot_hi[DIM * INNER], g_wot_lo[DIM * INNER];
__device__ __align__(256) bf16 g_qkv_hi[NSEQ * QKV3], g_qkv_lo[NSEQ * QKV3];
__device__ __align__(256) bf16 g_vt_hi[INNER * NSEQ], g_vt_lo[INNER * NSEQ];
__device__ __align__(256) bf16 g_at_hi[(size_t)HEADS * NSEQ * NSEQ];
__device__ __align__(256) bf16 g_at_lo[(size_t)HEADS * NSEQ * NSEQ];
__device__ __align__(256) bf16 g_o_hi[NSEQ * INNER],  g_o_lo[NSEQ * INNER];

// ---------------- helpers ------------------------------------------------------
__device__ __forceinline__ uint32_t smem_to_u32(const void* p) {
    uint32_t a;
    asm("{ .reg .u64 t; cvta.to.shared.u64 t, %1; cvt.u32.u64 %0, t; }"
        : "=r"(a) : "l"(p));
    return a;
}

__device__ __forceinline__ void ldmx4(uint32_t* r, uint32_t addr) {
    asm volatile("ldmatrix.sync.aligned.m8n8.x4.shared.b16 {%0,%1,%2,%3}, [%4];"
        : "=r"(r[0]), "=r"(r[1]), "=r"(r[2]), "=r"(r[3]) : "r"(addr));
}

__device__ __forceinline__ void mma_bf16(float* d, const uint32_t* a, const uint32_t* b) {
    asm volatile(
        "mma.sync.aligned.m16n8k16.row.col.f32.bf16.bf16.f32 "
        "{%0,%1,%2,%3}, {%4,%5,%6,%7}, {%8,%9}, {%0,%1,%2,%3};"
        : "+f"(d[0]), "+f"(d[1]), "+f"(d[2]), "+f"(d[3])
        : "r"(a[0]), "r"(a[1]), "r"(a[2]), "r"(a[3]), "r"(b[0]), "r"(b[1]));
}

__device__ __forceinline__ void mma_tf32(float* d, const uint32_t* a, uint32_t b0, uint32_t b1) {
    asm volatile(
        "mma.sync.aligned.m16n8k8.row.col.f32.tf32.tf32.f32 "
        "{%0,%1,%2,%3}, {%4,%5,%6,%7}, {%8,%9}, {%0,%1,%2,%3};"
        : "+f"(d[0]), "+f"(d[1]), "+f"(d[2]), "+f"(d[3])
        : "r"(a[0]), "r"(a[1]), "r"(a[2]), "r"(a[3]), "r"(b0), "r"(b1));
}

__device__ __forceinline__ void cp16(uint32_t sdst, const void* gsrc) {
    asm volatile("cp.async.cg.shared.global [%0], [%1], 16;"
                 :: "r"(sdst), "l"(__cvta_generic_to_global(gsrc)));
}
#define CP_COMMIT() asm volatile("cp.async.commit_group;" ::: "memory")
#define CP_WAIT(n)  asm volatile("cp.async.wait_group %0;" :: "n"(n) : "memory")

__device__ __forceinline__ uint32_t pack2(bf16 a, bf16 b) {
    __nv_bfloat162 t; t.x = a; t.y = b;
    uint32_t r; memcpy(&r, &t, 4); return r;
}

__device__ __forceinline__ void split1(float v, bf16& h, bf16& l) {
    h = __float2bfloat16(v);
    l = __float2bfloat16(v - __bfloat162float(h));
}

__device__ __forceinline__ uint32_t tf32hi(float v) {
    return __float_as_uint(v) & 0xFFFFE000u;
}
__device__ __forceinline__ uint32_t tf32lo(float v) {
    return __float_as_uint(v - __uint_as_float(__float_as_uint(v) & 0xFFFFE000u));
}

// ---------------- layernorm + split --------------------------------------------
__global__ void __launch_bounds__(256) ln_split(
    const float* __restrict__ x, const float* __restrict__ g,
    const float* __restrict__ b, bf16* __restrict__ xh, bf16* __restrict__ xl)
{
    __shared__ float r1[8], r2[8];
    int row = blockIdx.x;
    int tid = threadIdx.x;
    const float4 v = ((const float4*)(x + (size_t)row * DIM))[tid];

    float s  = v.x + v.y + v.z + v.w;
    float ss = v.x * v.x + v.y * v.y + v.z * v.z + v.w * v.w;
    #pragma unroll
    for (int o = 16; o; o >>= 1) {
        s  += __shfl_xor_sync(0xffffffffu, s,  o);
        ss += __shfl_xor_sync(0xffffffffu, ss, o);
    }
    int lane = tid & 31, wid = tid >> 5;
    if (lane == 0) { r1[wid] = s; r2[wid] = ss; }
    __syncthreads();
    float ts = 0.f, tss = 0.f;
    #pragma unroll
    for (int w = 0; w < 8; ++w) { ts += r1[w]; tss += r2[w]; }

    float mu  = ts * (1.0f / DIM);
    float var = tss * (1.0f / DIM) - mu * mu;
    float inv = rsqrtf(var + 1e-5f);

    float4 gg = ((const float4*)g)[tid];
    float4 bb = ((const float4*)b)[tid];
    float o0 = (v.x - mu) * inv * gg.x + bb.x;
    float o1 = (v.y - mu) * inv * gg.y + bb.y;
    float o2 = (v.z - mu) * inv * gg.z + bb.z;
    float o3 = (v.w - mu) * inv * gg.w + bb.w;

    bf16 h0,l0,h1,l1,h2,l2,h3,l3;
    split1(o0,h0,l0); split1(o1,h1,l1); split1(o2,h2,l2); split1(o3,h3,l3);
    uint2 hw = make_uint2(pack2(h0,h1), pack2(h2,h3));
    uint2 lw = make_uint2(pack2(l0,l1), pack2(l2,l3));
    *(uint2*)(xh + (size_t)row * DIM + tid * 4) = hw;
    *(uint2*)(xl + (size_t)row * DIM + tid * 4) = lw;
}

// ---------------- transpose + split weights: W[K,N] fp32 -> Wt[N,K] hi/lo ------
__global__ void __launch_bounds__(256) tsplit(
    const float* __restrict__ src, bf16* __restrict__ dh, bf16* __restrict__ dl,
    int K, int N)
{
    __shared__ float t[32][33];
    int n0 = blockIdx.x * 32, k0 = blockIdx.y * 32;
    int x = threadIdx.x, y = threadIdx.y;
    #pragma unroll
    for (int i = y; i < 32; i += 8)
        t[i][x] = src[(size_t)(k0 + i) * N + n0 + x];
    __syncthreads();
    #pragma unroll
    for (int i = y; i < 32; i += 8) {
        float v = t[x][i];                 // = src[k0+x][n0+i]
        bf16 h, l; split1(v, h, l);
        dh[(size_t)(n0 + i) * K + k0 + x] = h;
        dl[(size_t)(n0 + i) * K + k0 + x] = l;
    }
}

// ---------------- transpose v slice of qkv (bf16) into vt [1024][2048] ---------
__global__ void __launch_bounds__(256) vtrans(
    const bf16* __restrict__ ih, const bf16* __restrict__ il,
    bf16* __restrict__ oh, bf16* __restrict__ ol)
{
    __shared__ bf16 th[32][33], tl[32][33];
    int c0 = blockIdx.x * 32, j0 = blockIdx.y * 32;
    int x = threadIdx.x, y = threadIdx.y;
    #pragma unroll
    for (int i = y; i < 32; i += 8) {
        th[i][x] = ih[(size_t)(j0 + i) * QKV3 + 2 * INNER + c0 + x];
        tl[i][x] = il[(size_t)(j0 + i) * QKV3 + 2 * INNER + c0 + x];
    }
    __syncthreads();
    #pragma unroll
    for (int i = y; i < 32; i += 8) {
        oh[(size_t)(c0 + i) * NSEQ + j0 + x] = th[x][i];
        ol[(size_t)(c0 + i) * NSEQ + j0 + x] = tl[x][i];
    }
}

// ---------------- async tile loader: ROWS x 64 bf16, rows padded to 144B -------
template<int ROWS>
__device__ __forceinline__ void ld_tile(uint32_t sdst, const bf16* src, int ld, int tid) {
    #pragma unroll
    for (int it = 0; it < ROWS * 8 / 256; ++it) {
        int lin = tid + it * 256;
        int r  = lin >> 3;
        int cB = (lin & 7) << 4;
        cp16(sdst + r * 144 + cB, src + (size_t)r * ld + (cB >> 1));
    }
}

// ---------------- split-bf16 HMMA GEMM ------------------------------------------
// MODE 0: Cf = acc + bias   MODE 1: Chi/Clo = split(acc)   MODE 2: Cf = C_RAW*acc + C_H*Hin
template<int BN, int MODE>
__global__ void __launch_bounds__(256, 1) gemm_mma(
    const bf16* __restrict__ Ah, const bf16* __restrict__ Al,
    const bf16* __restrict__ Bh, const bf16* __restrict__ Bl,
    int K, int lda, int ldb,
    long long sA, long long sB, long long sC,
    float* __restrict__ Cf, bf16* __restrict__ Chi, bf16* __restrict__ Clo,
    int ldo, const float* __restrict__ bias, const float* __restrict__ Hin)
{
    constexpr int ROWB  = 144;
    constexpr int ATB   = 128 * ROWB;
    constexpr int BTB   = BN * ROWB;
    constexpr int STAGE = 2 * ATB + 2 * BTB;
    constexpr int NW_M  = (BN == 128) ? 2 : 4;
    constexpr int NW_N  = 8 / NW_M;
    constexpr int WM    = 128 / NW_M;
    constexpr int WN    = BN / NW_N;
    constexpr int MF    = WM / 16;
    constexpr int NF    = WN / 8;

    extern __shared__ char smem[];
    uint32_t smb = smem_to_u32(smem);

    int tid = threadIdx.x, lane = tid & 31, wid = tid >> 5;
    int z = blockIdx.z;
    int tm = blockIdx.y * 128, tn = blockIdx.x * BN;
    int wm = wid / NW_N, wn = wid % NW_N;

    const bf16* pAh = Ah + (size_t)z * sA + (size_t)tm * lda;
    const bf16* pAl = Al + (size_t)z * sA + (size_t)tm * lda;
    const bf16* pBh = Bh + (size_t)z * sB + (size_t)tn * ldb;
    const bf16* pBl = Bl + (size_t)z * sB + (size_t)tn * ldb;

    float acc[MF][NF][4];
    #pragma unroll
    for (int i = 0; i < MF; ++i)
        #pragma unroll
        for (int j = 0; j < NF; ++j)
            #pragma unroll
            for (int q = 0; q < 4; ++q) acc[i][j][q] = 0.f;

    const uint32_t aRow = (uint32_t)(wm * WM + (lane & 15)) * ROWB + ((lane >> 4) << 4);
    const uint32_t bRow = (uint32_t)(wn * WN + (lane & 7) + ((lane >> 4) << 3)) * ROWB
                        + (((lane >> 3) & 1) << 4);

    const int nc = K >> 6;

    ld_tile<128>(smb,                 pAh, lda, tid);
    ld_tile<128>(smb + ATB,           pAl, lda, tid);
    ld_tile<BN >(smb + 2*ATB,         pBh, ldb, tid);
    ld_tile<BN >(smb + 2*ATB + BTB,   pBl, ldb, tid);
    CP_COMMIT();

    for (int c = 0; c < nc; ++c) {
        int buf = c & 1;
        if (c + 1 < nc) {
            uint32_t nb = smb + ((c + 1) & 1) * STAGE;
            int koff = (c + 1) << 6;
            ld_tile<128>(nb,               pAh + koff, lda, tid);
            ld_tile<128>(nb + ATB,         pAl + koff, lda, tid);
            ld_tile<BN >(nb + 2*ATB,       pBh + koff, ldb, tid);
            ld_tile<BN >(nb + 2*ATB + BTB, pBl + koff, ldb, tid);
            CP_COMMIT();
            CP_WAIT(1);
        } else {
            CP_WAIT(0);
        }
        __syncthreads();

        uint32_t base = smb + buf * STAGE;
        #pragma unroll
        for (int ks = 0; ks < 4; ++ks) {
            uint32_t ah[MF][4], al[MF][4], bh[NF][2], bl[NF][2];
            #pragma unroll
            for (int fm = 0; fm < MF; ++fm) {
                uint32_t ra = base + aRow + fm * 16 * ROWB + ks * 32;
                ldmx4(ah[fm], ra);
                ldmx4(al[fm], ra + ATB);
            }
            #pragma unroll
            for (int f2 = 0; f2 < NF / 2; ++f2) {
                uint32_t rb = base + 2*ATB + bRow + f2 * 16 * ROWB + ks * 32;
                uint32_t r4[4];
                ldmx4(r4, rb);
                bh[2*f2][0] = r4[0]; bh[2*f2][1] = r4[1];
                bh[2*f2+1][0] = r4[2]; bh[2*f2+1][1] = r4[3];
                ldmx4(r4, rb + BTB);
                bl[2*f2][0] = r4[0]; bl[2*f2][1] = r4[1];
                bl[2*f2+1][0] = r4[2]; bl[2*f2+1][1] = r4[3];
            }
            #pragma unroll
            for (int fm = 0; fm < MF; ++fm)
                #pragma unroll
                for (int fn = 0; fn < NF; ++fn) {
                    mma_bf16(acc[fm][fn], ah[fm], bh[fn]);
                    mma_bf16(acc[fm][fn], ah[fm], bl[fn]);
                    mma_bf16(acc[fm][fn], al[fm], bh[fn]);
                }
        }
        __syncthreads();
    }

    #pragma unroll
    for (int fm = 0; fm < MF; ++fm) {
        int row0 = tm + wm * WM + fm * 16 + (lane >> 2);
        #pragma unroll
        for (int fn = 0; fn < NF; ++fn) {
            int col = tn + wn * WN + fn * 8 + ((lane & 3) << 1);
            const float* a4 = acc[fm][fn];
            if (MODE == 0) {
                float b0 = bias[col], b1 = bias[col + 1];
                float* p0 = Cf + (size_t)z * sC + (size_t)row0 * ldo + col;
                float* p1 = Cf + (size_t)z * sC + (size_t)(row0 + 8) * ldo + col;
                *(float2*)p0 = make_float2(a4[0] + b0, a4[1] + b1);
                *(float2*)p1 = make_float2(a4[2] + b0, a4[3] + b1);
            } else if (MODE == 1) {
                bf16 h0,l0,h1,l1;
                split1(a4[0], h0, l0); split1(a4[1], h1, l1);
                size_t off0 = (size_t)z * sC + (size_t)row0 * ldo + col;
                *(uint32_t*)(Chi + off0) = pack2(h0, h1);
                *(uint32_t*)(Clo + off0) = pack2(l0, l1);
                split1(a4[2], h0, l0); split1(a4[3], h1, l1);
                size_t off1 = (size_t)z * sC + (size_t)(row0 + 8) * ldo + col;
                *(uint32_t*)(Chi + off1) = pack2(h0, h1);
                *(uint32_t*)(Clo + off1) = pack2(l0, l1);
            } else {
                size_t off0 = (size_t)z * sC + (size_t)row0 * ldo + col;
                size_t off1 = (size_t)z * sC + (size_t)(row0 + 8) * ldo + col;
                float2 hv0 = *(const float2*)(Hin + off0);
                float2 hv1 = *(const float2*)(Hin + off1);
                *(float2*)(Cf + off0) = make_float2(C_RAW * a4[0] + C_H * hv0.x,
                                                    C_RAW * a4[1] + C_H * hv0.y);
                *(float2*)(Cf + off1) = make_float2(C_RAW * a4[2] + C_H * hv1.x,
                                                    C_RAW * a4[3] + C_H * hv1.y);
            }
        }
    }
}

// ---------------- fused talking-heads via tf32 MMA + warp-local softmax --------
// One CTA per query row i. tile[16][PITCH] fp32 in smem.
// Mix (16x16 @ 16xN) done with mma.m16n8k8.tf32, 3-pass hi/lo split.
__device__ __forceinline__ void prep_afrag(const float* m, int g, int kq,
                                           uint32_t* ah, uint32_t* al) {
    #pragma unroll
    for (int kb = 0; kb < 2; ++kb) {
        int k0 = kq + kb * 8;
        float v0 = m[(k0    ) * 16 + g];
        float v1 = m[(k0    ) * 16 + g + 8];
        float v2 = m[(k0 + 4) * 16 + g];
        float v3 = m[(k0 + 4) * 16 + g + 8];
        ah[kb*4+0] = tf32hi(v0); al[kb*4+0] = tf32lo(v0);
        ah[kb*4+1] = tf32hi(v1); al[kb*4+1] = tf32lo(v1);
        ah[kb*4+2] = tf32hi(v2); al[kb*4+2] = tf32lo(v2);
        ah[kb*4+3] = tf32hi(v3); al[kb*4+3] = tf32lo(v3);
    }
}

__device__ __forceinline__ void mix_block(const float* tile, int j, int kq,
                                          const uint32_t* ah, const uint32_t* al,
                                          float* d) {
    float v0 = tile[(kq     ) * PITCH + j];
    float v1 = tile[(kq +  4) * PITCH + j];
    float v2 = tile[(kq +  8) * PITCH + j];
    float v3 = tile[(kq + 12) * PITCH + j];
    uint32_t bh0 = tf32hi(v0), bl0 = tf32lo(v0);
    uint32_t bh1 = tf32hi(v1), bl1 = tf32lo(v1);
    uint32_t bh2 = tf32hi(v2), bl2 = tf32lo(v2);
    uint32_t bh3 = tf32hi(v3), bl3 = tf32lo(v3);
    d[0] = d[1] = d[2] = d[3] = 0.f;
    mma_tf32(d, ah + 0, bh0, bh1);
    mma_tf32(d, ah + 4, bh2, bh3);
    mma_tf32(d, ah + 0, bl0, bl1);
    mma_tf32(d, ah + 4, bl2, bl3);
    mma_tf32(d, al + 0, bh0, bh1);
    mma_tf32(d, al + 4, bh2, bh3);
}

__global__ void __launch_bounds__(256) mix_softmax(
    const float* __restrict__ blended, const float* __restrict__ mixpre,
    const float* __restrict__ mixpost, bf16* __restrict__ ath, bf16* __restrict__ atl)
{
    extern __shared__ float tile[];          // [16][PITCH]
    __shared__ float mp[256], mq[256];

    int i   = blockIdx.x;
    int tid = threadIdx.x;
    int lane = tid & 31, w = tid >> 5;

    mp[tid] = mixpre[tid];
    mq[tid] = mixpost[tid];

    // load 16 head-rows for this query
    #pragma unroll
    for (int h = 0; h < HEADS; ++h) {
        const float* src = blended + ((size_t)h * NSEQ + i) * NSEQ;
        for (int j = tid; j < NSEQ; j += 256) tile[h * PITCH + j] = src[j];
    }
    __syncthreads();

    int g  = lane >> 2;   // MMA row group / B col index
    int kq = lane & 3;    // MMA k quad

    // ---- pre-mix: dots = mp^T @ tile (in place, warp owns 32 8-col blocks) ----
    {
        uint32_t ah[8], al[8];
        prep_afrag(mp, g, kq, ah, al);
        for (int b = w * 32; b < w * 32 + 32; ++b) {
            float d[4];
            mix_block(tile, b * 8 + g, kq, ah, al, d);
            int jc = b * 8 + 2 * kq;
            *(float2*)&tile[(g    ) * PITCH + jc] = make_float2(d[0], d[1]);
            *(float2*)&tile[(g + 8) * PITCH + jc] = make_float2(d[2], d[3]);
        }
    }
    __syncthreads();

    // ---- warp-local softmax: warp w owns heads 2w, 2w+1 ----
    #pragma unroll
    for (int hh = 0; hh < 2; ++hh) {
        float* row = tile + (2 * w + hh) * PITCH;
        float m = -1e30f;
        for (int j = lane; j < NSEQ; j += 32) m = fmaxf(m, row[j]);
        #pragma unroll
        for (int o = 16; o; o >>= 1) m = fmaxf(m, __shfl_xor_sync(0xffffffffu, m, o));
        float s = 0.f;
        for (int j = lane; j < NSEQ; j += 32) {
            float e = __expf(row[j] - m);
            row[j] = e;
            s += e;
        }
        #pragma unroll
        for (int o = 16; o; o >>= 1) s += __shfl_xor_sync(0xffffffffu, s, o);
        float inv = 1.0f / s;
        for (int j = lane; j < NSEQ; j += 32) row[j] *= inv;
    }
    __syncthreads();

    // ---- post-mix: attn = mq^T @ probs, split hi/lo, straight to gmem ----
    {
        uint32_t ah[8], al[8];
        prep_afrag(mq, g, kq, ah, al);
        for (int b = w * 32; b < w * 32 + 32; ++b) {
            float d[4];
            mix_block(tile, b * 8 + g, kq, ah, al, d);
            int jc = b * 8 + 2 * kq;
            size_t o0 = ((size_t)(g    ) * NSEQ + i) * NSEQ + jc;
            size_t o1 = ((size_t)(g + 8) * NSEQ + i) * NSEQ + jc;
            bf16 h0, l0, h1, l1;
            split1(d[0], h0, l0); split1(d[1], h1, l1);
            *(uint32_t*)(ath + o0) = pack2(h0, h1);
            *(uint32_t*)(atl + o0) = pack2(l0, l1);
            split1(d[2], h0, l0); split1(d[3], h1, l1);
            *(uint32_t*)(ath + o1) = pack2(h0, h1);
            *(uint32_t*)(atl + o1) = pack2(l0, l1);
        }
    }
}

// ---------------- launch -------------------------------------------------------
extern "C" void kernel_launch(void* const* d_in, const int* in_sizes, int n_in,
                              void* d_out, int out_size)
{
    (void)in_sizes; (void)n_in; (void)out_size;
    const float* x     = (const float*)d_in[0];
    const float* h     = (const float*)d_in[1];
    const float* ln_g  = (const float*)d_in[2];
    const float* ln_b  = (const float*)d_in[3];
    const float* Wq    = (const float*)d_in[4];
    const float* Wkv   = (const float*)d_in[5];
    const float* mpre  = (const float*)d_in[6];
    const float* mpost = (const float*)d_in[7];
    const float* Wout  = (const float*)d_in[8];
    const float* bout  = (const float*)d_in[9];

    float* out     = (float*)d_out;
    float* blended = out + (size_t)NSEQ * DIM;

    bf16 *xnh,*xnl,*w1h,*w1l,*woh,*wol,*qkvh,*qkvl,*vth,*vtl,*ath,*atl,*oh,*ol;
    cudaGetSymbolAddress((void**)&xnh, g_xn_hi);  cudaGetSymbolAddress((void**)&xnl, g_xn_lo);
    cudaGetSymbolAddress((void**)&w1h, g_w1t_hi); cudaGetSymbolAddress((void**)&w1l, g_w1t_lo);
    cudaGetSymbolAddress((void**)&woh, g_wot_hi); cudaGetSymbolAddress((void**)&wol, g_wot_lo);
    cudaGetSymbolAddress((void**)&qkvh,g_qkv_hi); cudaGetSymbolAddress((void**)&qkvl,g_qkv_lo);
    cudaGetSymbolAddress((void**)&vth, g_vt_hi);  cudaGetSymbolAddress((void**)&vtl, g_vt_lo);
    cudaGetSymbolAddress((void**)&ath, g_at_hi);  cudaGetSymbolAddress((void**)&atl, g_at_lo);
    cudaGetSymbolAddress((void**)&oh,  g_o_hi);   cudaGetSymbolAddress((void**)&ol,  g_o_lo);

    const int SM128 = 2 * (2 * 128 * 144 + 2 * 128 * 144);  // 147456
    const int SM64  = 2 * (2 * 128 * 144 + 2 *  64 * 144);  // 110592
    const int SMIX  = HEADS * PITCH * (int)sizeof(float);    // 131584
    cudaFuncSetAttribute(gemm_mma<128,0>, cudaFuncAttributeMaxDynamicSharedMemorySize, SM128);
    cudaFuncSetAttribute(gemm_mma<128,1>, cudaFuncAttributeMaxDynamicSharedMemorySize, SM128);
    cudaFuncSetAttribute(gemm_mma<128,2>, cudaFuncAttributeMaxDynamicSharedMemorySize, SM128);
    cudaFuncSetAttribute(gemm_mma<64,1>,  cudaFuncAttributeMaxDynamicSharedMemorySize, SM64);
    cudaFuncSetAttribute(mix_softmax, cudaFuncAttributeMaxDynamicSharedMemorySize, SMIX);

    // 1. layernorm + split
    ln_split<<<NSEQ, 256>>>(x, ln_g, ln_b, xnh, xnl);

    // 2. weight transpose+split: [Wq^T; Wkv^T] into one buffer, Wout^T separate
    tsplit<<<dim3(INNER/32, DIM/32), dim3(32,8)>>>(Wq,  w1h, w1l, DIM, INNER);
    tsplit<<<dim3(KV2/32,   DIM/32), dim3(32,8)>>>(Wkv, w1h + (size_t)INNER*DIM,
                                                        w1l + (size_t)INNER*DIM, DIM, KV2);
    tsplit<<<dim3(DIM/32, INNER/32), dim3(32,8)>>>(Wout, woh, wol, INNER, DIM);

    // 3. qkv = xn @ [Wq Wkv]  (one N=3072 GEMM) -> hi/lo
    gemm_mma<128,1><<<dim3(QKV3/128, NSEQ/128, 1), 256, SM128>>>(
        xnh, xnl, w1h, w1l, DIM, DIM, DIM, 0, 0, 0,
        nullptr, qkvh, qkvl, QKV3, nullptr, nullptr);

    // 4. transpose v slice -> vt [1024][2048]
    vtrans<<<dim3(INNER/32, NSEQ/32), dim3(32,8)>>>(qkvh, qkvl, vth, vtl);

    // 5. blended = C_RAW * (q @ k^T) + C_H * h  -> d_out
    gemm_mma<128,2><<<dim3(NSEQ/128, NSEQ/128, HEADS), 256, SM128>>>(
        qkvh, qkvl, qkvh + INNER, qkvl + INNER, DH, QKV3, QKV3,
        DH, DH, (long long)NSEQ*NSEQ,
        blended, nullptr, nullptr, NSEQ, nullptr, h);

    // 6. mix_pre -> softmax -> mix_post -> attn hi/lo (tf32-MMA mixes)
    mix_softmax<<<NSEQ, 256, SMIX>>>(blended, mpre, mpost, ath, atl);

    // 7. o[:, g*64:] = attn[g] @ v_g   (per-head, BN=64)
    gemm_mma<64,1><<<dim3(1, NSEQ/128, HEADS), 256, SM64>>>(
        ath, atl, vth, vtl, NSEQ, NSEQ, NSEQ,
        (long long)NSEQ*NSEQ, (long long)DH*NSEQ, (long long)DH,
        nullptr, oh, ol, INNER, nullptr, nullptr);

    // 8. out = o @ Wout + bout
    gemm_mma<128,0><<<dim3(DIM/128, NSEQ/128, 1), 256, SM128>>>(
        oh, ol, woh, wol, INNER, INNER, INNER, 0, 0, 0,
        out, nullptr, nullptr, DIM, bout, nullptr);
}